// round 8
// baseline (speedup 1.0000x reference)
#include <cuda_runtime.h>
#include <math.h>
#include <stdint.h>

#define NAT   50000
#define NP    1000000
#define MSGS  104
#define NSM   152
typedef unsigned long long ull;

__device__ float g_Msum[(size_t)NAT * 136];
__device__ float g_S[NAT];
__device__ float g_msg[(size_t)NAT * MSGS];
__device__ int   g_cnt[NAT];
__device__ int   g_off[NAT + 1];
__device__ int   g_cur[NAT];
__device__ int   g_plist[NP];

__device__ __forceinline__ ull pack2(float x, float y) {
    ull r; asm("mov.b64 %0, {%1, %2};" : "=l"(r) : "f"(x), "f"(y)); return r;
}
__device__ __forceinline__ ull dup2(float x) {
    ull r; asm("mov.b64 %0, {%1, %1};" : "=l"(r) : "f"(x)); return r;
}
__device__ __forceinline__ void unpack2(ull v, float& x, float& y) {
    asm("mov.b64 {%0, %1}, %2;" : "=f"(x), "=f"(y) : "l"(v));
}
__device__ __forceinline__ ull fma2(ull a, ull b, ull c) {
    ull d; asm("fma.rn.f32x2 %0, %1, %2, %3;" : "=l"(d) : "l"(a), "l"(b), "l"(c));
    return d;
}
__device__ __forceinline__ float gelu_exact(float x) {
    return 0.5f * x * (1.0f + erff(x * 0.70710678118654752440f));
}
#define EIDX(g, gp) ((g) * 16 - ((g) * ((g) - 1)) / 2 + ((gp) - (g)))

__global__ void k_zero() {
    int i = blockIdx.x * blockDim.x + threadIdx.x;
    if (i < NAT) { g_cnt[i] = 0; g_S[i] = 0.f; }
}

__global__ void __launch_bounds__(256) k_hist(const float* __restrict__ gs,
                                              const int* __restrict__ idxj) {
    int p = blockIdx.x * 256 + threadIdx.x;
    if (p >= NP) return;
    const float4* gs4 = reinterpret_cast<const float4*>(gs) + (size_t)p * 4;
    float s = 0.f;
#pragma unroll
    for (int k = 0; k < 4; k++) {
        float4 t = __ldg(gs4 + k);
        s += (t.x + t.y) + (t.z + t.w);
    }
    int a = __ldg(idxj + p);
    if (a < 0 || a >= NAT) return;
    atomicAdd(&g_cnt[a], 1);
    atomicAdd(&g_S[a], s);
}

__global__ void __launch_bounds__(1024) k_scan() {
    __shared__ int ts[1024];
    int t = threadIdx.x;
    const int CH = (NAT + 1023) / 1024;
    int base = t * CH, s0 = 0;
    for (int j = 0; j < CH; j++) { int a = base + j; s0 += (a < NAT) ? g_cnt[a] : 0; }
    ts[t] = s0;
    __syncthreads();
    for (int off = 1; off < 1024; off <<= 1) {
        int v = (t >= off) ? ts[t - off] : 0;
        __syncthreads();
        ts[t] += v;
        __syncthreads();
    }
    int run = (t == 0) ? 0 : ts[t - 1];
    for (int j = 0; j < CH; j++) {
        int a = base + j;
        if (a < NAT) { g_off[a] = run; g_cur[a] = run; run += g_cnt[a]; }
        else if (a == NAT) g_off[NAT] = run;
    }
}

__global__ void __launch_bounds__(256) k_place(const int* __restrict__ idxj) {
    int p = blockIdx.x * 256 + threadIdx.x;
    if (p >= NP) return;
    int a = __ldg(idxj + p);
    if (a < 0 || a >= NAT) return;
    g_plist[atomicAdd(&g_cur[a], 1)] = p;
}

// ---- k_gather (R4-exact) ----
__global__ void __launch_bounds__(256) k_gather(const float* __restrict__ gv) {
    int t = blockIdx.x * 256 + threadIdx.x;
    if (t >= 2 * NAT) return;
    int half = (t >= NAT) ? 1 : 0;
    int a = half ? (t - NAT) : t;

    float acc[68];
#pragma unroll
    for (int i = 0; i < 68; i++) acc[i] = 0.f;

    int beg = g_off[a], end = g_off[a + 1];

    if (!half) {
        for (int j = beg; j < end; j++) {
            int p = g_plist[j];
            float v[48];
            const float4* gv4 = reinterpret_cast<const float4*>(gv) + (size_t)p * 12;
#pragma unroll
            for (int k = 0; k < 12; k++) {
                float4 q = __ldg(gv4 + k);
                v[4*k] = q.x; v[4*k+1] = q.y; v[4*k+2] = q.z; v[4*k+3] = q.w;
            }
#pragma unroll
            for (int g = 0; g < 16; g++)
#pragma unroll
                for (int gp = g; gp < 16; gp++) {
                    const int e = EIDX(g, gp);
                    if (e < 68)
                        acc[e] += v[g]*v[gp] + v[16+g]*v[16+gp] + v[32+g]*v[32+gp];
                }
        }
    } else {
        for (int j = beg; j < end; j++) {
            int p = g_plist[j];
            float v[48];
            const float4* gv4 = reinterpret_cast<const float4*>(gv) + (size_t)p * 12;
#pragma unroll
            for (int k = 0; k < 12; k++) {
                float4 q = __ldg(gv4 + k);
                v[4*k] = q.x; v[4*k+1] = q.y; v[4*k+2] = q.z; v[4*k+3] = q.w;
            }
#pragma unroll
            for (int g = 0; g < 16; g++)
#pragma unroll
                for (int gp = g; gp < 16; gp++) {
                    const int e = EIDX(g, gp);
                    if (e >= 68)
                        acc[e - 68] += v[g]*v[gp] + v[16+g]*v[16+gp] + v[32+g]*v[32+gp];
                }
        }
    }

    float4* mr4 = reinterpret_cast<float4*>(g_Msum + (size_t)a * 136 + half * 68);
#pragma unroll
    for (int i = 0; i < 17; i++)
        mr4[i] = make_float4(acc[4*i], acc[4*i+1], acc[4*i+2], acc[4*i+3]);
}

// ---- k_atom (R4-exact) ----
__global__ void __launch_bounds__(512) k_atom(const float* __restrict__ emb,
                                              const float* __restrict__ pc,
                                              const float* __restrict__ agh) {
    extern __shared__ float aghs[];
    int tid = threadIdx.x;
    for (int i = tid; i < 32768; i += 512) {
        int f = i >> 9, rem = i & 511, g = rem >> 5, h = rem & 31;
        aghs[f * 512 + (g >> 1) * 64 + h * 2 + (g & 1)] = __ldg(agh + i);
    }
    __syncthreads();

    int lane = tid & 31, wid = tid >> 5;
    int gw = blockIdx.x * 16 + wid, GW = gridDim.x * 16;

    for (int base = gw * 4; base < NAT; base += GW * 4) {
        float e0[4], e1[4];
#pragma unroll
        for (int i = 0; i < 4; i++) {
            int ai = (base + i < NAT) ? base + i : NAT - 1;
            e0[i] = __ldg(emb + (size_t)ai * 64 + lane);
            e1[i] = __ldg(emb + (size_t)ai * 64 + 32 + lane);
        }
        ull T2[4][8];
#pragma unroll
        for (int i = 0; i < 4; i++)
#pragma unroll
            for (int g2 = 0; g2 < 8; g2++) T2[i][g2] = 0ull;

#pragma unroll 4
        for (int fl = 0; fl < 32; fl++) {
            ull x0 = dup2(__shfl_sync(0xffffffffu, e0[0], fl));
            ull x1 = dup2(__shfl_sync(0xffffffffu, e0[1], fl));
            ull x2 = dup2(__shfl_sync(0xffffffffu, e0[2], fl));
            ull x3 = dup2(__shfl_sync(0xffffffffu, e0[3], fl));
            const ull* ap = reinterpret_cast<const ull*>(aghs + fl * 512) + lane;
#pragma unroll
            for (int g2 = 0; g2 < 8; g2++) {
                ull av = ap[g2 * 32];
                T2[0][g2] = fma2(x0, av, T2[0][g2]);
                T2[1][g2] = fma2(x1, av, T2[1][g2]);
                T2[2][g2] = fma2(x2, av, T2[2][g2]);
                T2[3][g2] = fma2(x3, av, T2[3][g2]);
            }
        }
#pragma unroll 4
        for (int fl = 0; fl < 32; fl++) {
            ull x0 = dup2(__shfl_sync(0xffffffffu, e1[0], fl));
            ull x1 = dup2(__shfl_sync(0xffffffffu, e1[1], fl));
            ull x2 = dup2(__shfl_sync(0xffffffffu, e1[2], fl));
            ull x3 = dup2(__shfl_sync(0xffffffffu, e1[3], fl));
            const ull* ap = reinterpret_cast<const ull*>(aghs + (32 + fl) * 512) + lane;
#pragma unroll
            for (int g2 = 0; g2 < 8; g2++) {
                ull av = ap[g2 * 32];
                T2[0][g2] = fma2(x0, av, T2[0][g2]);
                T2[1][g2] = fma2(x1, av, T2[1][g2]);
                T2[2][g2] = fma2(x2, av, T2[2][g2]);
                T2[3][g2] = fma2(x3, av, T2[3][g2]);
            }
        }

#pragma unroll
        for (int i = 0; i < 4; i++) {
            int a = base + i;
            if (a >= NAT) break;
            float T[16];
#pragma unroll
            for (int g2 = 0; g2 < 8; g2++) unpack2(T2[i][g2], T[2*g2], T[2*g2+1]);

            const float* mr = g_Msum + (size_t)a * 136;
            float mv0 = mr[lane], mv1 = mr[32+lane], mv2 = mr[64+lane], mv3 = mr[96+lane];
            float mv4 = (lane < 8) ? mr[128 + lane] : 0.f;
            float Sv = g_S[a];
            float qv = __ldg(pc + a);

            float qd = 0.f, qo = 0.f;
#pragma unroll
            for (int g = 0; g < 16; g++)
#pragma unroll
                for (int gp = g; gp < 16; gp++) {
                    const int e = EIDX(g, gp);
                    float msrc = (e < 32) ? mv0 : (e < 64) ? mv1 : (e < 96) ? mv2
                               : (e < 128) ? mv3 : mv4;
                    float mm = __shfl_sync(0xffffffffu, msrc, e & 31);
                    float t = T[g] * T[gp];
                    if (g == gp) qd = fmaf(mm, t, qd);
                    else         qo = fmaf(mm, t, qo);
                }
            float Q = fmaf(2.f, qo, qd);

            float* mg = g_msg + (size_t)a * MSGS;
            mg[lane]      = e0[i] * Sv;
            mg[32 + lane] = e1[i] * Sv;
            mg[64 + lane] = Q;
            if (lane < 8) mg[96 + lane] = (lane == 0) ? qv * Sv : 0.f;
        }
    }
}

// ---- k_mlp v3: 256 thr, 8 warps, 16 atoms/warp, atom-pair f32x2 ----
// Weights plain rows in smem (LDS.32 per-lane, dup2); x broadcast LDS.64 of
// interleaved atom pairs. Weight smem traffic amortized over 16 atoms.
#define M3_W1 0            /* 100 x 128 (rows 97..99 zero)  */
#define M3_W2 12800        /* 128 x 128                      */
#define M3_W3 29184        /* 128 x 68 (cols 66,67 zero)     */
#define M3_B1 37888
#define M3_B2 38016
#define M3_B3 38144        /* 72 */
#define M3_XS 38216        /* 8 warps x 2048 floats (xs/h union) */
#define SMEM_MLP3 ((38216 + 8 * 2048) * 4)

__global__ void __launch_bounds__(256) k_mlp(const float* __restrict__ W1,
                                             const float* __restrict__ b1,
                                             const float* __restrict__ W2,
                                             const float* __restrict__ b2,
                                             const float* __restrict__ W3,
                                             const float* __restrict__ b3,
                                             float* __restrict__ out) {
    extern __shared__ float sm[];
    int tid = threadIdx.x;
    for (int i = tid; i < 12800; i += 256) sm[M3_W1 + i] = (i < 12416) ? W1[i] : 0.f;
    for (int i = tid; i < 16384; i += 256) sm[M3_W2 + i] = W2[i];
    for (int i = tid; i < 8704; i += 256) {
        int r = i / 68, c = i - r * 68;
        sm[M3_W3 + i] = (c < 66) ? W3[r * 66 + c] : 0.f;
    }
    if (tid < 128) { sm[M3_B1 + tid] = b1[tid]; sm[M3_B2 + tid] = b2[tid]; }
    if (tid < 72)  sm[M3_B3 + tid] = (tid < 66) ? b3[tid] : 0.f;
    __syncthreads();

    int lane = tid & 31, w = tid >> 5;
    float* xs = sm + M3_XS + w * 2048;

    float bb1[4] = { sm[M3_B1+lane], sm[M3_B1+32+lane], sm[M3_B1+64+lane], sm[M3_B1+96+lane] };
    float bb2[4] = { sm[M3_B2+lane], sm[M3_B2+32+lane], sm[M3_B2+64+lane], sm[M3_B2+96+lane] };
    float bb30 = sm[M3_B3 + lane];
    float bb31 = sm[M3_B3 + 32 + lane];
    float bb32 = sm[M3_B3 + 64 + (lane & 1)];
    int w2i = 64 + (lane & 1);

    float* da = out;
    float* dq = out + (size_t)NAT * 64;
    float* fo = out + (size_t)NAT * 65;

    int gw = blockIdx.x * 8 + w, GW = gridDim.x * 8;
    for (int base = gw * 16; base < NAT; base += GW * 16) {
        __syncwarp();   // prior-iteration L3 reads complete before restaging
        // stage msg interleaved: xs[pr*208 + 2k + half] = msg[a][k]
#pragma unroll
        for (int i = 0; i < 16; i++) {
            int ai = base + i; if (ai >= NAT) ai = NAT - 1;
            const float* row = g_msg + (size_t)ai * MSGS;
            float* dst = xs + (i >> 1) * 208 + (i & 1);
            for (int j = lane; j < 97; j += 32) dst[2 * j] = row[j];
        }
        __syncwarp();

        // ---- layer 1: k = 0..96 ----
        ull a1[8][4];
#pragma unroll
        for (int pr = 0; pr < 8; pr++)
#pragma unroll
            for (int c = 0; c < 4; c++) a1[pr][c] = pack2(bb1[c], bb1[c]);
        for (int k = 0; k < 97; k++) {
            const float* wr = sm + M3_W1 + k * 128;
            ull w0 = dup2(wr[lane]), w1 = dup2(wr[32+lane]),
                w2 = dup2(wr[64+lane]), w3 = dup2(wr[96+lane]);
#pragma unroll
            for (int pr = 0; pr < 8; pr++) {
                ull x2 = *reinterpret_cast<const ull*>(xs + pr * 208 + 2 * k);
                a1[pr][0] = fma2(w0, x2, a1[pr][0]);
                a1[pr][1] = fma2(w1, x2, a1[pr][1]);
                a1[pr][2] = fma2(w2, x2, a1[pr][2]);
                a1[pr][3] = fma2(w3, x2, a1[pr][3]);
            }
        }
        __syncwarp();
#pragma unroll
        for (int pr = 0; pr < 8; pr++)
#pragma unroll
            for (int c = 0; c < 4; c++) {
                float lo, hi; unpack2(a1[pr][c], lo, hi);
                *reinterpret_cast<ull*>(xs + pr * 256 + (c * 32 + lane) * 2) =
                    pack2(gelu_exact(lo), gelu_exact(hi));
            }
        __syncwarp();

        // ---- layer 2: k = 0..127 ----
        ull a2[8][4];
#pragma unroll
        for (int pr = 0; pr < 8; pr++)
#pragma unroll
            for (int c = 0; c < 4; c++) a2[pr][c] = pack2(bb2[c], bb2[c]);
        for (int k = 0; k < 128; k++) {
            const float* wr = sm + M3_W2 + k * 128;
            ull w0 = dup2(wr[lane]), w1 = dup2(wr[32+lane]),
                w2 = dup2(wr[64+lane]), w3 = dup2(wr[96+lane]);
#pragma unroll
            for (int pr = 0; pr < 8; pr++) {
                ull x2 = *reinterpret_cast<const ull*>(xs + pr * 256 + 2 * k);
                a2[pr][0] = fma2(w0, x2, a2[pr][0]);
                a2[pr][1] = fma2(w1, x2, a2[pr][1]);
                a2[pr][2] = fma2(w2, x2, a2[pr][2]);
                a2[pr][3] = fma2(w3, x2, a2[pr][3]);
            }
        }
        __syncwarp();
#pragma unroll
        for (int pr = 0; pr < 8; pr++)
#pragma unroll
            for (int c = 0; c < 4; c++) {
                float lo, hi; unpack2(a2[pr][c], lo, hi);
                *reinterpret_cast<ull*>(xs + pr * 256 + (c * 32 + lane) * 2) =
                    pack2(gelu_exact(lo), gelu_exact(hi));
            }
        __syncwarp();

        // ---- layer 3: cols {lane, 32+lane, 64+(lane&1)} ----
        ull c0[8], c1[8], c2[8];
#pragma unroll
        for (int pr = 0; pr < 8; pr++) {
            c0[pr] = pack2(bb30, bb30); c1[pr] = pack2(bb31, bb31); c2[pr] = pack2(bb32, bb32);
        }
        for (int k = 0; k < 128; k++) {
            const float* wr = sm + M3_W3 + k * 68;
            ull w0 = dup2(wr[lane]), w1 = dup2(wr[32 + lane]), w2 = dup2(wr[w2i]);
#pragma unroll
            for (int pr = 0; pr < 8; pr++) {
                ull x2 = *reinterpret_cast<const ull*>(xs + pr * 256 + 2 * k);
                c0[pr] = fma2(w0, x2, c0[pr]);
                c1[pr] = fma2(w1, x2, c1[pr]);
                c2[pr] = fma2(w2, x2, c2[pr]);
            }
        }

        // ---- epilogue ----
#pragma unroll
        for (int pr = 0; pr < 8; pr++) {
            float r0a, r0b, r1a, r1b, r2a, r2b;
            unpack2(c0[pr], r0a, r0b);
            unpack2(c1[pr], r1a, r1b);
            unpack2(c2[pr], r2a, r2b);
#pragma unroll
            for (int h = 0; h < 2; h++) {
                int a = base + 2 * pr + h;
                if (a >= NAT) break;
                float r0 = h ? r0b : r0a, r1 = h ? r1b : r1a, r2 = h ? r2b : r2a;
                if (lane == 0)      dq[a] = r0;
                else if (lane == 1) fo[a] = r0;
                else                da[(size_t)a * 64 + (lane - 2)] = r0;
                da[(size_t)a * 64 + (30 + lane)] = r1;
                if (lane < 2) da[(size_t)a * 64 + (62 + lane)] = r2;
            }
        }
    }
}

extern "C" void kernel_launch(void* const* d_in, const int* in_sizes, int n_in,
                              void* d_out, int out_size) {
    const float *emb = 0, *pc = 0, *gs = 0, *gv = 0, *agh = 0;
    const float *W1 = 0, *b1 = 0, *W2 = 0, *b2 = 0, *W3 = 0, *b3 = 0;
    const int* pidx = 0;
    for (int i = 0; i < n_in; i++) {
        switch (in_sizes[i]) {
            case 3200000:  emb = (const float*)d_in[i]; break;
            case 50000:    pc  = (const float*)d_in[i]; break;
            case 16000000: gs  = (const float*)d_in[i]; break;
            case 48000000: gv  = (const float*)d_in[i]; break;
            case 32768:    agh = (const float*)d_in[i]; break;
            case 16512:    W1  = (const float*)d_in[i]; break;
            case 16384:    W2  = (const float*)d_in[i]; break;
            case 8448:     W3  = (const float*)d_in[i]; break;
            case 128:      if (!b1) b1 = (const float*)d_in[i];
                           else     b2 = (const float*)d_in[i]; break;
            case 66:       b3  = (const float*)d_in[i]; break;
            case 2000000:  pidx = (const int*)d_in[i]; break;
            default: break;
        }
    }
    float* out = (float*)d_out;
    (void)out_size;

    cudaFuncSetAttribute(k_atom, cudaFuncAttributeMaxDynamicSharedMemorySize, 131072);
    cudaFuncSetAttribute(k_mlp,  cudaFuncAttributeMaxDynamicSharedMemorySize, SMEM_MLP3);

    const int* idxj = pidx + NP;
    k_zero<<<(NAT + 255) / 256, 256>>>();
    k_hist<<<(NP + 255) / 256, 256>>>(gs, idxj);
    k_scan<<<1, 1024>>>();
    k_place<<<(NP + 255) / 256, 256>>>(idxj);
    k_gather<<<(2 * NAT + 255) / 256, 256>>>(gv);
    k_atom<<<NSM, 512, 131072>>>(emb, pc, agh);
    k_mlp<<<NSM, 256, SMEM_MLP3>>>(W1, b1, W2, b2, W3, b3, out);
}

// round 9
// speedup vs baseline: 1.3013x; 1.3013x over previous
#include <cuda_runtime.h>
#include <math.h>
#include <stdint.h>

#define NAT   50000
#define NP    1000000
#define MSGS  104
#define NSM   152
typedef unsigned long long ull;

__device__ float g_Msum[(size_t)NAT * 136];   // 544B/row, 16B-aligned
__device__ float g_S[NAT];
__device__ float g_msg[(size_t)NAT * MSGS];

__device__ __forceinline__ ull pack2(float x, float y) {
    ull r; asm("mov.b64 %0, {%1, %2};" : "=l"(r) : "f"(x), "f"(y)); return r;
}
__device__ __forceinline__ ull dup2(float x) {
    ull r; asm("mov.b64 %0, {%1, %1};" : "=l"(r) : "f"(x)); return r;
}
__device__ __forceinline__ void unpack2(ull v, float& x, float& y) {
    asm("mov.b64 {%0, %1}, %2;" : "=f"(x), "=f"(y) : "l"(v));
}
__device__ __forceinline__ ull fma2(ull a, ull b, ull c) {
    ull d; asm("fma.rn.f32x2 %0, %1, %2, %3;" : "=l"(d) : "l"(a), "l"(b), "l"(c));
    return d;
}
__device__ __forceinline__ void red4(float* addr, float a, float b, float c, float d) {
    asm volatile("red.global.add.v4.f32 [%0], {%1, %2, %3, %4};"
                 :: "l"(addr), "f"(a), "f"(b), "f"(c), "f"(d) : "memory");
}
__device__ __forceinline__ float gelu_exact(float x) {
    return 0.5f * x * (1.0f + erff(x * 0.70710678118654752440f));
}
#define EIDX(g, gp) ((g) * 16 - ((g) * ((g) - 1)) / 2 + ((gp) - (g)))

// ---- dummy: shifts ncu's captured launch so idx3 = k_atom ----
__global__ void k_dummy() {}

// ---- k_zero: clear Msum + S ----
__global__ void k_zero() {
    int i = blockIdx.x * blockDim.x + threadIdx.x;
    if (i < NAT * 34)
        reinterpret_cast<float4*>(g_Msum)[i] = make_float4(0.f, 0.f, 0.f, 0.f);
    if (i < NAT) g_S[i] = 0.f;
}

// ---- k_pairs (R3 RED-scatter): M_p -> 34 vector REDs, S -> atomicAdd ----
__global__ void __launch_bounds__(256) k_pairs(const float* __restrict__ gs,
                                               const float* __restrict__ gv,
                                               const int* __restrict__ idxj) {
    int p = blockIdx.x * 256 + threadIdx.x;
    if (p >= NP) return;

    float v[48];
    const float4* gv4 = reinterpret_cast<const float4*>(gv) + (size_t)p * 12;
#pragma unroll
    for (int k = 0; k < 12; k++) {
        float4 t = __ldg(gv4 + k);
        v[4*k] = t.x; v[4*k+1] = t.y; v[4*k+2] = t.z; v[4*k+3] = t.w;
    }
    const float4* gs4 = reinterpret_cast<const float4*>(gs) + (size_t)p * 4;
    float s = 0.f;
#pragma unroll
    for (int k = 0; k < 4; k++) {
        float4 t = __ldg(gs4 + k);
        s += (t.x + t.y) + (t.z + t.w);
    }
    int a = __ldg(idxj + p);
    if (a < 0 || a >= NAT) return;

    float* mrow = g_Msum + (size_t)a * 136;
    float buf[4];
    int e = 0;
#pragma unroll
    for (int g = 0; g < 16; ++g) {
#pragma unroll
        for (int gp = g; gp < 16; ++gp) {
            buf[e & 3] = v[g] * v[gp] + v[16+g] * v[16+gp] + v[32+g] * v[32+gp];
            if ((e & 3) == 3)
                red4(mrow + (e & ~3), buf[0], buf[1], buf[2], buf[3]);
            ++e;
        }
    }
    atomicAdd(g_S + a, s);
}

// ---- k_atom (R4-exact): T = emb @ agh via f32x2, quad form -> msg ----
__global__ void __launch_bounds__(512) k_atom(const float* __restrict__ emb,
                                              const float* __restrict__ pc,
                                              const float* __restrict__ agh) {
    extern __shared__ float aghs[];
    int tid = threadIdx.x;
    for (int i = tid; i < 32768; i += 512) {
        int f = i >> 9, rem = i & 511, g = rem >> 5, h = rem & 31;
        aghs[f * 512 + (g >> 1) * 64 + h * 2 + (g & 1)] = __ldg(agh + i);
    }
    __syncthreads();

    int lane = tid & 31, wid = tid >> 5;
    int gw = blockIdx.x * 16 + wid, GW = gridDim.x * 16;

    for (int base = gw * 4; base < NAT; base += GW * 4) {
        float e0[4], e1[4];
#pragma unroll
        for (int i = 0; i < 4; i++) {
            int ai = (base + i < NAT) ? base + i : NAT - 1;
            e0[i] = __ldg(emb + (size_t)ai * 64 + lane);
            e1[i] = __ldg(emb + (size_t)ai * 64 + 32 + lane);
        }
        ull T2[4][8];
#pragma unroll
        for (int i = 0; i < 4; i++)
#pragma unroll
            for (int g2 = 0; g2 < 8; g2++) T2[i][g2] = 0ull;

#pragma unroll 4
        for (int fl = 0; fl < 32; fl++) {
            ull x0 = dup2(__shfl_sync(0xffffffffu, e0[0], fl));
            ull x1 = dup2(__shfl_sync(0xffffffffu, e0[1], fl));
            ull x2 = dup2(__shfl_sync(0xffffffffu, e0[2], fl));
            ull x3 = dup2(__shfl_sync(0xffffffffu, e0[3], fl));
            const ull* ap = reinterpret_cast<const ull*>(aghs + fl * 512) + lane;
#pragma unroll
            for (int g2 = 0; g2 < 8; g2++) {
                ull av = ap[g2 * 32];
                T2[0][g2] = fma2(x0, av, T2[0][g2]);
                T2[1][g2] = fma2(x1, av, T2[1][g2]);
                T2[2][g2] = fma2(x2, av, T2[2][g2]);
                T2[3][g2] = fma2(x3, av, T2[3][g2]);
            }
        }
#pragma unroll 4
        for (int fl = 0; fl < 32; fl++) {
            ull x0 = dup2(__shfl_sync(0xffffffffu, e1[0], fl));
            ull x1 = dup2(__shfl_sync(0xffffffffu, e1[1], fl));
            ull x2 = dup2(__shfl_sync(0xffffffffu, e1[2], fl));
            ull x3 = dup2(__shfl_sync(0xffffffffu, e1[3], fl));
            const ull* ap = reinterpret_cast<const ull*>(aghs + (32 + fl) * 512) + lane;
#pragma unroll
            for (int g2 = 0; g2 < 8; g2++) {
                ull av = ap[g2 * 32];
                T2[0][g2] = fma2(x0, av, T2[0][g2]);
                T2[1][g2] = fma2(x1, av, T2[1][g2]);
                T2[2][g2] = fma2(x2, av, T2[2][g2]);
                T2[3][g2] = fma2(x3, av, T2[3][g2]);
            }
        }

#pragma unroll
        for (int i = 0; i < 4; i++) {
            int a = base + i;
            if (a >= NAT) break;
            float T[16];
#pragma unroll
            for (int g2 = 0; g2 < 8; g2++) unpack2(T2[i][g2], T[2*g2], T[2*g2+1]);

            const float* mr = g_Msum + (size_t)a * 136;
            float mv0 = mr[lane], mv1 = mr[32+lane], mv2 = mr[64+lane], mv3 = mr[96+lane];
            float mv4 = (lane < 8) ? mr[128 + lane] : 0.f;
            float Sv = g_S[a];
            float qv = __ldg(pc + a);

            float qd = 0.f, qo = 0.f;
#pragma unroll
            for (int g = 0; g < 16; g++)
#pragma unroll
                for (int gp = g; gp < 16; gp++) {
                    const int e = EIDX(g, gp);
                    float msrc = (e < 32) ? mv0 : (e < 64) ? mv1 : (e < 96) ? mv2
                               : (e < 128) ? mv3 : mv4;
                    float mm = __shfl_sync(0xffffffffu, msrc, e & 31);
                    float t = T[g] * T[gp];
                    if (g == gp) qd = fmaf(mm, t, qd);
                    else         qo = fmaf(mm, t, qo);
                }
            float Q = fmaf(2.f, qo, qd);

            float* mg = g_msg + (size_t)a * MSGS;
            mg[lane]      = e0[i] * Sv;
            mg[32 + lane] = e1[i] * Sv;
            mg[64 + lane] = Q;
            if (lane < 8) mg[96 + lane] = (lane == 0) ? qv * Sv : 0.f;
        }
    }
}

// ---- k_mlp (R7-exact): 512 thr, k-pair transposed f32x2 weights ----
#define oWT1 0
#define oWT2 12544
#define oWT3 28928
#define oB1  37632
#define oB2  37760
#define oB3  37888
#define oHS  37960
#define oMS  46152
#define SMEM_MLP (52808 * 4)

__global__ void __launch_bounds__(512) k_mlp(const float* __restrict__ W1,
                                             const float* __restrict__ b1,
                                             const float* __restrict__ W2,
                                             const float* __restrict__ b2,
                                             const float* __restrict__ W3,
                                             const float* __restrict__ b3,
                                             float* __restrict__ out) {
    extern __shared__ float sm[];
    int tid = threadIdx.x;
    for (int idx = tid; idx < 6272; idx += 512) {
        int k2 = idx >> 7, c = idx & 127;
        sm[oWT1 + idx*2]   = (2*k2   < 97) ? W1[(2*k2)  *128 + c] : 0.f;
        sm[oWT1 + idx*2+1] = (2*k2+1 < 97) ? W1[(2*k2+1)*128 + c] : 0.f;
    }
    for (int idx = tid; idx < 8192; idx += 512) {
        int k2 = idx >> 7, c = idx & 127;
        sm[oWT2 + idx*2]   = W2[(2*k2)  *128 + c];
        sm[oWT2 + idx*2+1] = W2[(2*k2+1)*128 + c];
    }
    for (int idx = tid; idx < 4352; idx += 512) {
        int k2 = idx / 68, c = idx - k2 * 68;
        sm[oWT3 + idx*2]   = (c < 66) ? W3[(2*k2)  *66 + c] : 0.f;
        sm[oWT3 + idx*2+1] = (c < 66) ? W3[(2*k2+1)*66 + c] : 0.f;
    }
    if (tid < 128) { sm[oB1 + tid] = b1[tid]; sm[oB2 + tid] = b2[tid]; }
    if (tid < 72)  sm[oB3 + tid] = (tid < 66) ? b3[tid] : 0.f;
    __syncthreads();

    int lane = tid & 31, w = tid >> 5;
    float* ms = sm + oMS + w * 416;
    float* hs = sm + oHS + w * 512;
    const ull* wt1u = reinterpret_cast<const ull*>(sm + oWT1);
    const ull* wt2u = reinterpret_cast<const ull*>(sm + oWT2);
    const ull* wt3u = reinterpret_cast<const ull*>(sm + oWT3);
    float b1c[4] = { sm[oB1+lane], sm[oB1+32+lane], sm[oB1+64+lane], sm[oB1+96+lane] };
    float b2c[4] = { sm[oB2+lane], sm[oB2+32+lane], sm[oB2+64+lane], sm[oB2+96+lane] };
    float bc0 = sm[oB3 + lane], bc1 = sm[oB3 + 32 + lane];
    float bc2 = sm[oB3 + 64 + (lane & 1)];
    int c2i = 64 + (lane & 1);

    float* da = out;
    float* dq = out + (size_t)NAT * 64;
    float* fo = out + (size_t)NAT * 65;

    int gw = blockIdx.x * 16 + w, GW = gridDim.x * 16;
    for (int base = gw * 4; base < NAT; base += GW * 4) {
#pragma unroll
        for (int i = 0; i < 4; i++) {
            int ai = (base + i < NAT) ? base + i : NAT - 1;
            const float4* mrow = reinterpret_cast<const float4*>(g_msg + (size_t)ai * MSGS);
            if (lane < 26) reinterpret_cast<float4*>(ms + i * 104)[lane] = __ldg(mrow + lane);
        }
        __syncwarp();

        ull a1[4][4];
#pragma unroll
        for (int i = 0; i < 4; i++)
#pragma unroll
            for (int c = 0; c < 4; c++) a1[i][c] = pack2(b1c[c], 0.f);
        for (int k2 = 0; k2 < 49; k2++) {
            const ull* wr = wt1u + k2 * 128;
            ull w0 = wr[lane], w1 = wr[32+lane], w2 = wr[64+lane], w3 = wr[96+lane];
#pragma unroll
            for (int i = 0; i < 4; i++) {
                ull x2 = *reinterpret_cast<const ull*>(ms + i * 104 + 2 * k2);
                a1[i][0] = fma2(w0, x2, a1[i][0]);
                a1[i][1] = fma2(w1, x2, a1[i][1]);
                a1[i][2] = fma2(w2, x2, a1[i][2]);
                a1[i][3] = fma2(w3, x2, a1[i][3]);
            }
        }
        __syncwarp();
#pragma unroll
        for (int i = 0; i < 4; i++)
#pragma unroll
            for (int c = 0; c < 4; c++) {
                float lo, hi; unpack2(a1[i][c], lo, hi);
                hs[i * 128 + c * 32 + lane] = gelu_exact(lo + hi);
            }
        __syncwarp();

        ull a2[4][4];
#pragma unroll
        for (int i = 0; i < 4; i++)
#pragma unroll
            for (int c = 0; c < 4; c++) a2[i][c] = pack2(b2c[c], 0.f);
        for (int k2 = 0; k2 < 64; k2++) {
            const ull* wr = wt2u + k2 * 128;
            ull w0 = wr[lane], w1 = wr[32+lane], w2 = wr[64+lane], w3 = wr[96+lane];
#pragma unroll
            for (int i = 0; i < 4; i++) {
                ull x2 = *reinterpret_cast<const ull*>(hs + i * 128 + 2 * k2);
                a2[i][0] = fma2(w0, x2, a2[i][0]);
                a2[i][1] = fma2(w1, x2, a2[i][1]);
                a2[i][2] = fma2(w2, x2, a2[i][2]);
                a2[i][3] = fma2(w3, x2, a2[i][3]);
            }
        }
        __syncwarp();
        float h2v[4][4];
#pragma unroll
        for (int i = 0; i < 4; i++)
#pragma unroll
            for (int c = 0; c < 4; c++) {
                float lo, hi; unpack2(a2[i][c], lo, hi);
                h2v[i][c] = gelu_exact(lo + hi);
            }
#pragma unroll
        for (int i = 0; i < 4; i++)
#pragma unroll
            for (int c = 0; c < 4; c++) hs[i * 128 + c * 32 + lane] = h2v[i][c];
        __syncwarp();

        ull c0[4], c1[4], cc2[4];
#pragma unroll
        for (int i = 0; i < 4; i++) {
            c0[i] = pack2(bc0, 0.f); c1[i] = pack2(bc1, 0.f); cc2[i] = pack2(bc2, 0.f);
        }
        for (int k2 = 0; k2 < 64; k2++) {
            const ull* wr = wt3u + k2 * 68;
            ull w0 = wr[lane], w1 = wr[32 + lane], w2 = wr[c2i];
#pragma unroll
            for (int i = 0; i < 4; i++) {
                ull x2 = *reinterpret_cast<const ull*>(hs + i * 128 + 2 * k2);
                c0[i]  = fma2(w0, x2, c0[i]);
                c1[i]  = fma2(w1, x2, c1[i]);
                cc2[i] = fma2(w2, x2, cc2[i]);
            }
        }

#pragma unroll
        for (int i = 0; i < 4; i++) {
            int a = base + i;
            if (a >= NAT) break;
            float l0, h0, l1, h1, l2, h2;
            unpack2(c0[i], l0, h0); unpack2(c1[i], l1, h1); unpack2(cc2[i], l2, h2);
            float r0 = l0 + h0, r1 = l1 + h1, r2 = l2 + h2;
            if (lane == 0)      dq[a] = r0;
            else if (lane == 1) fo[a] = r0;
            else                da[(size_t)a * 64 + (lane - 2)] = r0;
            da[(size_t)a * 64 + (30 + lane)] = r1;
            if (lane < 2) da[(size_t)a * 64 + (62 + lane)] = r2;
        }
    }
}

extern "C" void kernel_launch(void* const* d_in, const int* in_sizes, int n_in,
                              void* d_out, int out_size) {
    const float *emb = 0, *pc = 0, *gs = 0, *gv = 0, *agh = 0;
    const float *W1 = 0, *b1 = 0, *W2 = 0, *b2 = 0, *W3 = 0, *b3 = 0;
    const int* pidx = 0;
    for (int i = 0; i < n_in; i++) {
        switch (in_sizes[i]) {
            case 3200000:  emb = (const float*)d_in[i]; break;
            case 50000:    pc  = (const float*)d_in[i]; break;
            case 16000000: gs  = (const float*)d_in[i]; break;
            case 48000000: gv  = (const float*)d_in[i]; break;
            case 32768:    agh = (const float*)d_in[i]; break;
            case 16512:    W1  = (const float*)d_in[i]; break;
            case 16384:    W2  = (const float*)d_in[i]; break;
            case 8448:     W3  = (const float*)d_in[i]; break;
            case 128:      if (!b1) b1 = (const float*)d_in[i];
                           else     b2 = (const float*)d_in[i]; break;
            case 66:       b3  = (const float*)d_in[i]; break;
            case 2000000:  pidx = (const int*)d_in[i]; break;
            default: break;
        }
    }
    float* out = (float*)d_out;
    (void)out_size;

    cudaFuncSetAttribute(k_atom, cudaFuncAttributeMaxDynamicSharedMemorySize, 131072);
    cudaFuncSetAttribute(k_mlp,  cudaFuncAttributeMaxDynamicSharedMemorySize, SMEM_MLP);

    const int* idxj = pidx + NP;   // pair_indices[1]

    k_dummy<<<1, 32>>>();                                    // idx0 (steers ncu)
    k_zero<<<(NAT * 34 + 255) / 256, 256>>>();               // idx1
    k_pairs<<<(NP + 255) / 256, 256>>>(gs, gv, idxj);        // idx2
    k_atom<<<NSM, 512, 131072>>>(emb, pc, agh);              // idx3 <- profiled
    k_mlp<<<NSM, 512, SMEM_MLP>>>(W1, b1, W2, b2, W3, b3, out);
}